// round 6
// baseline (speedup 1.0000x reference)
#include <cuda_runtime.h>

#define BN 8
#define CC 192
#define CQ 32
#define NN 16384
#define EPSV 1e-6f

typedef unsigned long long u64;

__device__ __forceinline__ u64 pk2(float lo, float hi) {
    u64 r; asm("mov.b64 %0,{%1,%2};" : "=l"(r) : "f"(lo), "f"(hi)); return r;
}
__device__ __forceinline__ void upk2(float& lo, float& hi, u64 v) {
    asm("mov.b64 {%0,%1},%2;" : "=f"(lo), "=f"(hi) : "l"(v));
}
__device__ __forceinline__ u64 fma2(u64 a, u64 b, u64 c) {
    u64 d; asm("fma.rn.f32x2 %0,%1,%2,%3;" : "=l"(d) : "l"(a), "l"(b), "l"(c)); return d;
}
__device__ __forceinline__ u64 mul2(u64 a, u64 b) {
    u64 d; asm("mul.rn.f32x2 %0,%1,%2;" : "=l"(d) : "l"(a), "l"(b)); return d;
}
__device__ __forceinline__ u64 add2(u64 a, u64 b) {
    u64 d; asm("add.rn.f32x2 %0,%1,%2;" : "=l"(d) : "l"(a), "l"(b)); return d;
}

// Scratch (device globals: no allocation allowed)
__device__ float g_Qn[BN*CQ*NN];     // normalized Q, [b][m][n] plain
__device__ u64   g_Kn2[BN*CQ*NN];    // normalized K, duplicated {k,k} per n
__device__ float g_Ksum[BN*CQ];
__device__ float g_xsum[BN*CC];
__device__ float g_M1[BN*CQ*CC];
__device__ float g_mat[BN*CQ*CC];
__device__ float g_vsum[BN*CC];

__global__ void zero_kernel() {
    int i = blockIdx.x * blockDim.x + threadIdx.x;
    int stride = gridDim.x * blockDim.x;
    for (int j = i; j < BN*CQ; j += stride) g_Ksum[j] = 0.f;
    for (int j = i; j < BN*CC; j += stride) { g_xsum[j] = 0.f; g_vsum[j] = 0.f; }
    for (int j = i; j < BN*CQ*CC; j += stride) { g_M1[j] = 0.f; g_mat[j] = 0.f; }
}

// ---------------------------------------------------------------------------
// Q/K projection + L2 norm. x1 read direct from gmem (L1-reused across warps),
// weights pre-duplicated {w,w} in smem. Software pipeline: x loads one
// c4-group ahead. Block 256, n-tile 128, thread tile 8m x 4n.
// tid = qk*128 + mg*32 + nt. smem = wdup 98304B + psum 4096B = 102400B -> occ 2.
// ---------------------------------------------------------------------------
__global__ void __launch_bounds__(256, 2) qk_kernel(
    const float* __restrict__ x1,
    const float* __restrict__ Wq, const float* __restrict__ bq,
    const float* __restrict__ Wk, const float* __restrict__ bk)
{
    extern __shared__ u64 smq[];
    u64*   wdup = smq;                       // [c][64] : m0-31=Q, m32-63=K
    float* psum = (float*)(wdup + CC*64);    // [256][4]

    int tid = threadIdx.x;
    int b   = blockIdx.y;
    int nb  = blockIdx.x * 128;

    // stage duplicated weights
    for (int i = tid; i < CQ*CC; i += 256) {
        int m = i / CC, c = i % CC;
        float wq = Wq[i], wk = Wk[i];
        wdup[c*64 + m]      = pk2(wq, wq);
        wdup[c*64 + 32 + m] = pk2(wk, wk);
    }
    __syncthreads();

    int qk = tid >> 7;
    int r  = tid & 127;
    int mg = r >> 5;
    int nt = r & 31;
    int n0 = nt * 4;

    const u64*   wbase = wdup + qk*32 + mg*8;
    const float* bias  = qk ? bk : bq;
    const float* xp    = x1 + (size_t)(b*CC)*NN + nb + n0;

    u64 acc[16];   // [mi][pr]: pr0=(n0,n1), pr1=(n2,n3)
#pragma unroll
    for (int mi = 0; mi < 8; mi++) {
        float bb = __ldg(&bias[mg*8 + mi]);
        u64 b2 = pk2(bb, bb);
        acc[mi*2] = b2; acc[mi*2+1] = b2;
    }

    // software pipeline over groups of 4 c's
    ulonglong2 xv[4], xn[4];
#pragma unroll
    for (int t = 0; t < 4; t++)
        xv[t] = *(const ulonglong2*)(xp + (size_t)t*NN);

    for (int c4 = 0; c4 < CC; c4 += 4) {
        int cn = (c4 + 4 < CC) ? (c4 + 4) : (CC - 4);   // clamp: avoid OOB
#pragma unroll
        for (int t = 0; t < 4; t++)
            xn[t] = *(const ulonglong2*)(xp + (size_t)(cn + t)*NN);
#pragma unroll
        for (int t = 0; t < 4; t++) {
            const ulonglong2* wr = (const ulonglong2*)(wbase + (c4 + t)*64);
            ulonglong2 w01 = wr[0], w23 = wr[1], w45 = wr[2], w67 = wr[3];
            ulonglong2 xvt = xv[t];
            acc[0]  = fma2(w01.x, xvt.x, acc[0]);  acc[1]  = fma2(w01.x, xvt.y, acc[1]);
            acc[2]  = fma2(w01.y, xvt.x, acc[2]);  acc[3]  = fma2(w01.y, xvt.y, acc[3]);
            acc[4]  = fma2(w23.x, xvt.x, acc[4]);  acc[5]  = fma2(w23.x, xvt.y, acc[5]);
            acc[6]  = fma2(w23.y, xvt.x, acc[6]);  acc[7]  = fma2(w23.y, xvt.y, acc[7]);
            acc[8]  = fma2(w45.x, xvt.x, acc[8]);  acc[9]  = fma2(w45.x, xvt.y, acc[9]);
            acc[10] = fma2(w45.y, xvt.x, acc[10]); acc[11] = fma2(w45.y, xvt.y, acc[11]);
            acc[12] = fma2(w67.x, xvt.x, acc[12]); acc[13] = fma2(w67.x, xvt.y, acc[13]);
            acc[14] = fma2(w67.y, xvt.x, acc[14]); acc[15] = fma2(w67.y, xvt.y, acc[15]);
        }
#pragma unroll
        for (int t = 0; t < 4; t++) xv[t] = xn[t];
    }

    // partial sum of squares per n (this thread's 8 m's)
    float s0 = 0.f, s1 = 0.f, s2 = 0.f, s3 = 0.f;
#pragma unroll
    for (int mi = 0; mi < 8; mi++) {
        float l0, h0, l1, h1;
        upk2(l0, h0, acc[mi*2]);
        upk2(l1, h1, acc[mi*2+1]);
        s0 += l0*l0; s1 += h0*h0; s2 += l1*l1; s3 += h1*h1;
    }
    psum[tid*4+0] = s0; psum[tid*4+1] = s1;
    psum[tid*4+2] = s2; psum[tid*4+3] = s3;
    __syncthreads();

    float t0 = 0.f, t1 = 0.f, t2 = 0.f, t3 = 0.f;
#pragma unroll
    for (int g = 0; g < 4; g++) {
        int p = (qk*128 + g*32 + nt)*4;
        t0 += psum[p]; t1 += psum[p+1]; t2 += psum[p+2]; t3 += psum[p+3];
    }
    u64 inv01 = pk2(rsqrtf(t0), rsqrtf(t1));
    u64 inv23 = pk2(rsqrtf(t2), rsqrtf(t3));

    if (qk == 0) {
#pragma unroll
        for (int mi = 0; mi < 8; mi++) {
            ulonglong2 st;
            st.x = mul2(acc[mi*2],   inv01);
            st.y = mul2(acc[mi*2+1], inv23);
            *(ulonglong2*)(g_Qn + (size_t)(b*CQ + mg*8 + mi)*NN + nb + n0) = st;
        }
    } else {
#pragma unroll
        for (int mi = 0; mi < 8; mi++) {
            u64 p0 = mul2(acc[mi*2],   inv01);
            u64 p1 = mul2(acc[mi*2+1], inv23);
            float l0, h0, l1, h1;
            upk2(l0, h0, p0); upk2(l1, h1, p1);
            // duplicated store for m1
            ulonglong2* kp = (ulonglong2*)(g_Kn2 + (size_t)(b*CQ + mg*8 + mi)*NN + nb + n0);
            ulonglong2 d01, d23;
            d01.x = pk2(l0, l0); d01.y = pk2(h0, h0);
            d23.x = pk2(l1, l1); d23.y = pk2(h1, h1);
            kp[0] = d01; kp[1] = d23;
            float kv = (l0 + h0) + (l1 + h1);
#pragma unroll
            for (int o = 16; o; o >>= 1) kv += __shfl_xor_sync(0xffffffffu, kv, o);
            if (nt == 0) atomicAdd(&g_Ksum[b*CQ + mg*8 + mi], kv);
        }
    }
}

// ---------------------------------------------------------------------------
// M1[b,m,p] = sum_n Kn[b,m,n]*x[b,p,n]; xsum[b,p] = sum_n x[b,p,n]
// Block 192: tid = jh*96 + mh*48 + pq. Thread tile: 16 m x 4 p, packed over p.
// occ 3 so load phases overlap across CTAs.
// ---------------------------------------------------------------------------
__global__ void __launch_bounds__(192, 3) m1_kernel(const float* __restrict__ x)
{
    __shared__ float xs[32*196];      // [j][p], pad 196
    __shared__ u64 kst2[32*34];       // [j][m] duplicated {k,k}, pad 34

    int tid = threadIdx.x;
    int b = blockIdx.y;
    int nbase = blockIdx.x * 512;

    int jh = tid / 96;
    int rr = tid % 96;
    int mh = rr / 48;
    int pq = rr % 48;

    u64 a[32];
#pragma unroll
    for (int k = 0; k < 32; k++) a[k] = 0ULL;
    u64 xsA = 0ULL, xsB = 0ULL;

    for (int s = 0; s < 16; s++) {
        int n0 = nbase + s*32;
        __syncthreads();
        for (int i = tid; i < CC*32; i += 192) {
            int p = i >> 5, j = i & 31;
            xs[j*196 + p] = x[(size_t)(b*CC + p)*NN + n0 + j];
        }
        for (int i = tid; i < CQ*32; i += 192) {
            int m = i >> 5, j = i & 31;
            kst2[j*34 + m] = g_Kn2[(size_t)(b*CQ + m)*NN + n0 + j];
        }
        __syncthreads();

        int jbeg = jh * 16;
#pragma unroll 2
        for (int jj = 0; jj < 16; jj++) {
            int j = jbeg + jj;
            ulonglong2 xv = *(const ulonglong2*)(xs + j*196 + 4*pq);
            xsA = add2(xsA, xv.x);
            xsB = add2(xsB, xv.y);
            const ulonglong2* kr = (const ulonglong2*)(kst2 + j*34 + mh*16);
#pragma unroll
            for (int mm = 0; mm < 8; mm++) {
                ulonglong2 kk = kr[mm];
                a[mm*4+0] = fma2(kk.x, xv.x, a[mm*4+0]);
                a[mm*4+1] = fma2(kk.x, xv.y, a[mm*4+1]);
                a[mm*4+2] = fma2(kk.y, xv.x, a[mm*4+2]);
                a[mm*4+3] = fma2(kk.y, xv.y, a[mm*4+3]);
            }
        }
    }

    // combine jh halves via smem, then atomics from jh==0
    __syncthreads();
    u64* comb = (u64*)xs;   // 96*32 u64 = 24576 B <= xs size
    int slot = mh*48 + pq;
    if (jh == 1) {
#pragma unroll
        for (int k = 0; k < 32; k++) comb[slot*32 + k] = a[k];
    }
    __syncthreads();
    if (jh == 0) {
#pragma unroll
        for (int k = 0; k < 32; k++) {
            u64 t = add2(a[k], comb[slot*32 + k]);
            float lo, hi; upk2(lo, hi, t);
            int m = mh*16 + ((k >> 2) << 1) + ((k >> 1) & 1);
            int p = 4*pq + ((k & 1) << 1);
            atomicAdd(&g_M1[(b*CQ + m)*CC + p],     lo);
            atomicAdd(&g_M1[(b*CQ + m)*CC + p + 1], hi);
        }
    }
    if (mh == 0 && jh == 0) {
        float l0, h0, l1, h1;
        upk2(l0, h0, xsA); upk2(l1, h1, xsB);
        atomicAdd(&g_xsum[b*CC + 4*pq + 0], l0);
        atomicAdd(&g_xsum[b*CC + 4*pq + 1], h0);
        atomicAdd(&g_xsum[b*CC + 4*pq + 2], l1);
        atomicAdd(&g_xsum[b*CC + 4*pq + 3], h1);
    }
    if (mh == 0 && jh == 1) {
        float l0, h0, l1, h1;
        upk2(l0, h0, xsA); upk2(l1, h1, xsB);
        atomicAdd(&g_xsum[b*CC + 4*pq + 0], l0);
        atomicAdd(&g_xsum[b*CC + 4*pq + 1], h0);
        atomicAdd(&g_xsum[b*CC + 4*pq + 2], l1);
        atomicAdd(&g_xsum[b*CC + 4*pq + 3], h1);
    }
}

// ---------------------------------------------------------------------------
// matrix[b,m,c] = sum_p Wv[c,p]*M1[b,m,p] + bv[c]*Ksum[b,m]
// vsum[b,c]    = sum_p Wv[c,p]*xsum[b,p] + N*bv[c]
// grid (BN, 16), block 192 (one thread per c), 12 p per block.
// ---------------------------------------------------------------------------
__global__ void __launch_bounds__(192) mat_kernel(
    const float* __restrict__ Wv, const float* __restrict__ bv)
{
    __shared__ float m1t[CC][36];   // [p][m]
    __shared__ float xs_s[CC];
    int tid = threadIdx.x;
    int b  = blockIdx.x;
    int pg = blockIdx.y;  // 0..15, 12 p's each

    for (int i = tid; i < CQ*CC; i += 192) {
        int m = i / CC, p = i % CC;
        m1t[p][m] = g_M1[b*CQ*CC + i];
    }
    xs_s[tid] = g_xsum[b*CC + tid];
    __syncthreads();

    int c = tid;
    float accm[CQ];
#pragma unroll
    for (int m = 0; m < CQ; m++) accm[m] = 0.f;
    float vs = 0.f;

    for (int p = pg*12; p < (pg+1)*12; p++) {
        float wv = __ldg(&Wv[c*CC + p]);
        vs += wv * xs_s[p];
        const float4* row = (const float4*)&m1t[p][0];
#pragma unroll
        for (int m4 = 0; m4 < 8; m4++) {
            float4 mv = row[m4];
            accm[m4*4+0] += wv*mv.x;
            accm[m4*4+1] += wv*mv.y;
            accm[m4*4+2] += wv*mv.z;
            accm[m4*4+3] += wv*mv.w;
        }
    }
    if (pg == 0) {
        float bvc = __ldg(&bv[c]);
        vs += (float)NN * bvc;
#pragma unroll
        for (int m = 0; m < CQ; m++) accm[m] += bvc * g_Ksum[b*CQ + m];
    }
    atomicAdd(&g_vsum[b*CC + c], vs);
#pragma unroll
    for (int m = 0; m < CQ; m++) atomicAdd(&g_mat[(b*CQ + m)*CC + c], accm[m]);
}

// ---------------------------------------------------------------------------
// out[b,c,n] = gamma*tailor[b,n]*(vsum[b,c] + sum_m Qn[b,m,n]*matrix[b,m,c])
// Block 128, each thread one n-pair. grid (NN/256, BN) = (64, 8).
// ---------------------------------------------------------------------------
__global__ void __launch_bounds__(128) final_kernel(
    float* __restrict__ out, const float* __restrict__ gamma)
{
    extern __shared__ u64 smf[];
    u64* mat2 = smf;                 // 192*34
    u64* vs2  = mat2 + 192*34;       // 192
    u64* kse2 = vs2 + 192;           // 32

    int tid = threadIdx.x;
    int b = blockIdx.y;

    for (int i = tid; i < CQ*CC; i += 128) {
        int m = i / CC, c = i % CC;
        float v = g_mat[b*CQ*CC + i];
        mat2[c*34 + m] = pk2(v, v);
    }
    for (int i = tid; i < CC; i += 128) { float v = g_vsum[b*CC + i]; vs2[i] = pk2(v, v); }
    if (tid < CQ) { float v = g_Ksum[b*CQ + tid] + EPSV; kse2[tid] = pk2(v, v); }
    __syncthreads();

    int n0 = (blockIdx.x * 128 + tid) * 2;

    u64 q2[CQ];
#pragma unroll
    for (int m = 0; m < CQ; m++)
        q2[m] = *(const u64*)(g_Qn + (size_t)(b*CQ + m)*NN + n0);

    // tailor: sum over ALL 32 m
    u64 t0 = pk2((float)NN, (float)NN), t1 = 0ULL, t2 = 0ULL, t3 = 0ULL;
#pragma unroll
    for (int mh = 0; mh < 8; mh++) {
        ulonglong2 ke0 = ((const ulonglong2*)kse2)[2*mh];
        ulonglong2 ke1 = ((const ulonglong2*)kse2)[2*mh+1];
        t0 = fma2(q2[4*mh+0], ke0.x, t0);
        t1 = fma2(q2[4*mh+1], ke0.y, t1);
        t2 = fma2(q2[4*mh+2], ke1.x, t2);
        t3 = fma2(q2[4*mh+3], ke1.y, t3);
    }
    u64 tt = add2(add2(t0, t1), add2(t2, t3));
    float tl, th; upk2(tl, th, tt);
    float gm = __ldg(&gamma[0]);
    u64 scale2 = pk2(gm / tl, gm / th);

    float* op = out + (size_t)(b*CC)*NN + n0;
#pragma unroll 2
    for (int c = 0; c < CC; c++) {
        u64 a0 = vs2[c], a1 = 0ULL, a2 = 0ULL, a3 = 0ULL;
        const ulonglong2* row = (const ulonglong2*)(mat2 + c*34);
#pragma unroll
        for (int m4 = 0; m4 < 8; m4++) {
            ulonglong2 w0 = row[2*m4];
            ulonglong2 w1 = row[2*m4+1];
            a0 = fma2(w0.x, q2[4*m4],   a0);
            a1 = fma2(w0.y, q2[4*m4+1], a1);
            a2 = fma2(w1.x, q2[4*m4+2], a2);
            a3 = fma2(w1.y, q2[4*m4+3], a3);
        }
        u64 res = mul2(add2(add2(a0, a1), add2(a2, a3)), scale2);
        *(u64*)(op + (size_t)c*NN) = res;
    }
}

extern "C" void kernel_launch(void* const* d_in, const int* in_sizes, int n_in,
                              void* d_out, int out_size) {
    const float* x     = (const float*)d_in[0];
    const float* x1    = (const float*)d_in[1];
    const float* Wq    = (const float*)d_in[2];
    const float* bq    = (const float*)d_in[3];
    const float* Wk    = (const float*)d_in[4];
    const float* bk    = (const float*)d_in[5];
    const float* Wv    = (const float*)d_in[6];
    const float* bv    = (const float*)d_in[7];
    const float* gamma = (const float*)d_in[8];
    float* out = (float*)d_out;

    const int qk_smem  = CC*64*8 + 256*4*4;            // 98304 + 4096 = 102400 B
    const int fin_smem = (192*34 + 192 + 32) * 8;      // 54016 B
    cudaFuncSetAttribute(qk_kernel, cudaFuncAttributeMaxDynamicSharedMemorySize, qk_smem);
    cudaFuncSetAttribute(final_kernel, cudaFuncAttributeMaxDynamicSharedMemorySize, fin_smem);

    zero_kernel<<<96, 256>>>();
    qk_kernel<<<dim3(NN/128, BN), 256, qk_smem>>>(x1, Wq, bq, Wk, bk);
    m1_kernel<<<dim3(NN/512, BN), 192>>>(x);
    mat_kernel<<<dim3(BN, 16), 192>>>(Wv, bv);
    final_kernel<<<dim3(NN/256, BN), 128, fin_smem>>>(out, gamma);
}

// round 7
// speedup vs baseline: 1.5126x; 1.5126x over previous
#include <cuda_runtime.h>

#define BN 8
#define CC 192
#define CQ 32
#define NN 16384
#define EPSV 1e-6f

typedef unsigned long long u64;

__device__ __forceinline__ u64 pk2(float lo, float hi) {
    u64 r; asm("mov.b64 %0,{%1,%2};" : "=l"(r) : "f"(lo), "f"(hi)); return r;
}
__device__ __forceinline__ void upk2(float& lo, float& hi, u64 v) {
    asm("mov.b64 {%0,%1},%2;" : "=f"(lo), "=f"(hi) : "l"(v));
}
__device__ __forceinline__ u64 fma2(u64 a, u64 b, u64 c) {
    u64 d; asm("fma.rn.f32x2 %0,%1,%2,%3;" : "=l"(d) : "l"(a), "l"(b), "l"(c)); return d;
}
__device__ __forceinline__ u64 mul2(u64 a, u64 b) {
    u64 d; asm("mul.rn.f32x2 %0,%1,%2;" : "=l"(d) : "l"(a), "l"(b)); return d;
}
__device__ __forceinline__ u64 add2(u64 a, u64 b) {
    u64 d; asm("add.rn.f32x2 %0,%1,%2;" : "=l"(d) : "l"(a), "l"(b)); return d;
}

// Scratch (device globals: no allocation allowed)
__device__ float g_Qn[BN*CQ*NN];
__device__ float g_Kn[BN*CQ*NN];
__device__ float g_Ksum[BN*CQ];
__device__ float g_xsum[BN*CC];
__device__ float g_M1[BN*CQ*CC];
__device__ float g_mat[BN*CQ*CC];
__device__ float g_vsum[BN*CC];

__global__ void zero_kernel() {
    int i = blockIdx.x * blockDim.x + threadIdx.x;
    int stride = gridDim.x * blockDim.x;
    for (int j = i; j < BN*CQ; j += stride) g_Ksum[j] = 0.f;
    for (int j = i; j < BN*CC; j += stride) { g_xsum[j] = 0.f; g_vsum[j] = 0.f; }
    for (int j = i; j < BN*CQ*CC; j += stride) { g_M1[j] = 0.f; g_mat[j] = 0.f; }
}

// ---------------------------------------------------------------------------
// Q/K projection + L2 norm, packed f32x2 over n.
// Block 256, n-tile 128. Thread tile: 8 m x 4 n.
// tid = qk*128 + mg*32 + nt.
// smem: wdup[c][64] u64 (m0-31=Q dup'd, m32-63=K dup'd) + xs[192][128] + psum.
// Inner loop: 5 LDS.128 + 16 FMA2 per c — no per-iteration MOV duplication.
// ---------------------------------------------------------------------------
__global__ void __launch_bounds__(256, 1) qk_kernel(
    const float* __restrict__ x1,
    const float* __restrict__ Wq, const float* __restrict__ bq,
    const float* __restrict__ Wk, const float* __restrict__ bk)
{
    extern __shared__ u64 smq[];
    u64*   wdup = smq;                       // 192*64 u64 = 98304 B
    float* xs   = (float*)(wdup + CC*64);    // 192*128 f32 = 98304 B
    float* psum = xs + 192*128;              // 1024 f32 = 4096 B

    int tid = threadIdx.x;
    int b   = blockIdx.y;
    int nb  = blockIdx.x * 128;

    // stage x1 tile [c][n]
    for (int i = tid; i < 192*32; i += 256) {
        int c = i >> 5, jj = i & 31;
        *(float4*)(xs + c*128 + 4*jj) =
            *(const float4*)(x1 + (size_t)(b*CC + c)*NN + nb + 4*jj);
    }
    // stage duplicated weights
    for (int i = tid; i < CQ*CC; i += 256) {
        int m = i / CC, c = i % CC;
        float wq = Wq[i], wk = Wk[i];
        wdup[c*64 + m]      = pk2(wq, wq);
        wdup[c*64 + 32 + m] = pk2(wk, wk);
    }
    __syncthreads();

    int qk = tid >> 7;
    int r  = tid & 127;
    int mg = r >> 5;
    int nt = r & 31;
    int n0 = nt * 4;

    const u64*   wbase = wdup + qk*32 + mg*8;
    const float* bias  = qk ? bk : bq;

    u64 acc[16];   // [mi][pr]: pr0=(n0,n1), pr1=(n2,n3)
#pragma unroll
    for (int mi = 0; mi < 8; mi++) {
        float bb = __ldg(&bias[mg*8 + mi]);
        u64 b2 = pk2(bb, bb);
        acc[mi*2] = b2; acc[mi*2+1] = b2;
    }

#pragma unroll 4
    for (int c = 0; c < CC; c++) {
        ulonglong2 xv = *(const ulonglong2*)(xs + c*128 + n0);
        const ulonglong2* wr = (const ulonglong2*)(wbase + c*64);
        ulonglong2 w01 = wr[0], w23 = wr[1], w45 = wr[2], w67 = wr[3];
        acc[0]  = fma2(w01.x, xv.x, acc[0]);  acc[1]  = fma2(w01.x, xv.y, acc[1]);
        acc[2]  = fma2(w01.y, xv.x, acc[2]);  acc[3]  = fma2(w01.y, xv.y, acc[3]);
        acc[4]  = fma2(w23.x, xv.x, acc[4]);  acc[5]  = fma2(w23.x, xv.y, acc[5]);
        acc[6]  = fma2(w23.y, xv.x, acc[6]);  acc[7]  = fma2(w23.y, xv.y, acc[7]);
        acc[8]  = fma2(w45.x, xv.x, acc[8]);  acc[9]  = fma2(w45.x, xv.y, acc[9]);
        acc[10] = fma2(w45.y, xv.x, acc[10]); acc[11] = fma2(w45.y, xv.y, acc[11]);
        acc[12] = fma2(w67.x, xv.x, acc[12]); acc[13] = fma2(w67.x, xv.y, acc[13]);
        acc[14] = fma2(w67.y, xv.x, acc[14]); acc[15] = fma2(w67.y, xv.y, acc[15]);
    }

    // partial sum of squares per n (this thread's 8 m's)
    float s0 = 0.f, s1 = 0.f, s2 = 0.f, s3 = 0.f;
#pragma unroll
    for (int mi = 0; mi < 8; mi++) {
        float l0, h0, l1, h1;
        upk2(l0, h0, acc[mi*2]);
        upk2(l1, h1, acc[mi*2+1]);
        s0 += l0*l0; s1 += h0*h0; s2 += l1*l1; s3 += h1*h1;
    }
    psum[tid*4+0] = s0; psum[tid*4+1] = s1;
    psum[tid*4+2] = s2; psum[tid*4+3] = s3;
    __syncthreads();

    float t0 = 0.f, t1 = 0.f, t2 = 0.f, t3 = 0.f;
#pragma unroll
    for (int g = 0; g < 4; g++) {
        int p = (qk*128 + g*32 + nt)*4;
        t0 += psum[p]; t1 += psum[p+1]; t2 += psum[p+2]; t3 += psum[p+3];
    }
    u64 inv01 = pk2(rsqrtf(t0), rsqrtf(t1));
    u64 inv23 = pk2(rsqrtf(t2), rsqrtf(t3));

    if (qk == 0) {
#pragma unroll
        for (int mi = 0; mi < 8; mi++) {
            ulonglong2 st;
            st.x = mul2(acc[mi*2],   inv01);
            st.y = mul2(acc[mi*2+1], inv23);
            *(ulonglong2*)(g_Qn + (size_t)(b*CQ + mg*8 + mi)*NN + nb + n0) = st;
        }
    } else {
#pragma unroll
        for (int mi = 0; mi < 8; mi++) {
            ulonglong2 st;
            st.x = mul2(acc[mi*2],   inv01);
            st.y = mul2(acc[mi*2+1], inv23);
            *(ulonglong2*)(g_Kn + (size_t)(b*CQ + mg*8 + mi)*NN + nb + n0) = st;
            float l0, h0, l1, h1;
            upk2(l0, h0, st.x); upk2(l1, h1, st.y);
            float kv = (l0 + h0) + (l1 + h1);
#pragma unroll
            for (int o = 16; o; o >>= 1) kv += __shfl_xor_sync(0xffffffffu, kv, o);
            if (nt == 0) atomicAdd(&g_Ksum[b*CQ + mg*8 + mi], kv);
        }
    }
}

// ---------------------------------------------------------------------------
// M1[b,m,p] = sum_n Kn[b,m,n]*x[b,p,n]; xsum[b,p] = sum_n x[b,p,n]
// Block 192: tid = jh*96 + mh*48 + pq. Thread tile: 16 m x 4 p, packed over p.
// Double-buffered staging: load subtile s+1 while computing s.
// ---------------------------------------------------------------------------
__global__ void __launch_bounds__(192, 2) m1_kernel(const float* __restrict__ x)
{
    __shared__ float xs[2][32*196];   // [buf][j][p], pad 196
    __shared__ u64 kst2[2][32*34];    // [buf][j][m] duplicated {k,k}, pad 34

    int tid = threadIdx.x;
    int b = blockIdx.y;
    int nbase = blockIdx.x * 512;

    int jh = tid / 96;
    int rr = tid % 96;
    int mh = rr / 48;
    int pq = rr % 48;

    u64 a[32];
#pragma unroll
    for (int k = 0; k < 32; k++) a[k] = 0ULL;
    u64 xsA = 0ULL, xsB = 0ULL;

    // prologue: load subtile 0 into buffer 0
    {
        int n0 = nbase;
        for (int i = tid; i < CC*32; i += 192) {
            int p = i >> 5, j = i & 31;
            xs[0][j*196 + p] = x[(size_t)(b*CC + p)*NN + n0 + j];
        }
        for (int i = tid; i < CQ*32; i += 192) {
            int m = i >> 5, j = i & 31;
            float v = g_Kn[(size_t)(b*CQ + m)*NN + n0 + j];
            kst2[0][j*34 + m] = pk2(v, v);
        }
    }
    __syncthreads();

    for (int s = 0; s < 16; s++) {
        int cur = s & 1, nxt = cur ^ 1;
        if (s + 1 < 16) {
            int n1 = nbase + (s+1)*32;
            for (int i = tid; i < CC*32; i += 192) {
                int p = i >> 5, j = i & 31;
                xs[nxt][j*196 + p] = x[(size_t)(b*CC + p)*NN + n1 + j];
            }
            for (int i = tid; i < CQ*32; i += 192) {
                int m = i >> 5, j = i & 31;
                float v = g_Kn[(size_t)(b*CQ + m)*NN + n1 + j];
                kst2[nxt][j*34 + m] = pk2(v, v);
            }
        }

        int jbeg = jh * 16;
#pragma unroll 2
        for (int jj = 0; jj < 16; jj++) {
            int j = jbeg + jj;
            ulonglong2 xv = *(const ulonglong2*)(&xs[cur][j*196 + 4*pq]);
            xsA = add2(xsA, xv.x);
            xsB = add2(xsB, xv.y);
            const ulonglong2* kr = (const ulonglong2*)(&kst2[cur][j*34 + mh*16]);
#pragma unroll
            for (int mm = 0; mm < 8; mm++) {
                ulonglong2 kk = kr[mm];
                a[mm*4+0] = fma2(kk.x, xv.x, a[mm*4+0]);
                a[mm*4+1] = fma2(kk.x, xv.y, a[mm*4+1]);
                a[mm*4+2] = fma2(kk.y, xv.x, a[mm*4+2]);
                a[mm*4+3] = fma2(kk.y, xv.y, a[mm*4+3]);
            }
        }
        __syncthreads();
    }

    // combine jh halves via smem, then atomics from jh==0
    u64* comb = (u64*)&xs[0][0];   // 96*32 u64 = 24576 B <= buffer 0
    int slot = mh*48 + pq;
    if (jh == 1) {
#pragma unroll
        for (int k = 0; k < 32; k++) comb[slot*32 + k] = a[k];
    }
    __syncthreads();
    if (jh == 0) {
#pragma unroll
        for (int k = 0; k < 32; k++) {
            u64 t = add2(a[k], comb[slot*32 + k]);
            float lo, hi; upk2(lo, hi, t);
            int m = mh*16 + ((k >> 2) << 1) + ((k >> 1) & 1);
            int p = 4*pq + ((k & 1) << 1);
            atomicAdd(&g_M1[(b*CQ + m)*CC + p],     lo);
            atomicAdd(&g_M1[(b*CQ + m)*CC + p + 1], hi);
        }
    }
    if (mh == 0) {
        float l0, h0, l1, h1;
        upk2(l0, h0, xsA); upk2(l1, h1, xsB);
        atomicAdd(&g_xsum[b*CC + 4*pq + 0], l0);
        atomicAdd(&g_xsum[b*CC + 4*pq + 1], h0);
        atomicAdd(&g_xsum[b*CC + 4*pq + 2], l1);
        atomicAdd(&g_xsum[b*CC + 4*pq + 3], h1);
    }
}

// ---------------------------------------------------------------------------
// matrix[b,m,c] = sum_p Wv[c,p]*M1[b,m,p] + bv[c]*Ksum[b,m]
// vsum[b,c]    = sum_p Wv[c,p]*xsum[b,p] + N*bv[c]
// grid (BN, 16), block 192 (one thread per c), 12 p per block.
// ---------------------------------------------------------------------------
__global__ void __launch_bounds__(192) mat_kernel(
    const float* __restrict__ Wv, const float* __restrict__ bv)
{
    __shared__ float m1t[CC][36];   // [p][m]
    __shared__ float xs_s[CC];
    int tid = threadIdx.x;
    int b  = blockIdx.x;
    int pg = blockIdx.y;  // 0..15, 12 p's each

    for (int i = tid; i < CQ*CC; i += 192) {
        int m = i / CC, p = i % CC;
        m1t[p][m] = g_M1[b*CQ*CC + i];
    }
    xs_s[tid] = g_xsum[b*CC + tid];
    __syncthreads();

    int c = tid;
    float accm[CQ];
#pragma unroll
    for (int m = 0; m < CQ; m++) accm[m] = 0.f;
    float vs = 0.f;

    for (int p = pg*12; p < (pg+1)*12; p++) {
        float wv = __ldg(&Wv[c*CC + p]);
        vs += wv * xs_s[p];
        const float4* row = (const float4*)&m1t[p][0];
#pragma unroll
        for (int m4 = 0; m4 < 8; m4++) {
            float4 mv = row[m4];
            accm[m4*4+0] += wv*mv.x;
            accm[m4*4+1] += wv*mv.y;
            accm[m4*4+2] += wv*mv.z;
            accm[m4*4+3] += wv*mv.w;
        }
    }
    if (pg == 0) {
        float bvc = __ldg(&bv[c]);
        vs += (float)NN * bvc;
#pragma unroll
        for (int m = 0; m < CQ; m++) accm[m] += bvc * g_Ksum[b*CQ + m];
    }
    atomicAdd(&g_vsum[b*CC + c], vs);
#pragma unroll
    for (int m = 0; m < CQ; m++) atomicAdd(&g_mat[(b*CQ + m)*CC + c], accm[m]);
}

// ---------------------------------------------------------------------------
// out[b,c,n] = gamma*tailor[b,n]*(vsum[b,c] + sum_m Qn[b,m,n]*matrix[b,m,c])
// Packed over n: 2 n per thread. Block 256, grid (NN/512, BN).
// ---------------------------------------------------------------------------
__global__ void __launch_bounds__(256) final_kernel(
    float* __restrict__ out, const float* __restrict__ gamma)
{
    extern __shared__ u64 smf[];
    u64* mat2 = smf;                 // 192*34
    u64* vs2  = mat2 + 192*34;       // 192
    u64* kse2 = vs2 + 192;           // 32

    int tid = threadIdx.x;
    int b = blockIdx.y;

    for (int i = tid; i < CQ*CC; i += 256) {
        int m = i / CC, c = i % CC;
        float v = g_mat[b*CQ*CC + i];
        mat2[c*34 + m] = pk2(v, v);
    }
    if (tid < CC) { float v = g_vsum[b*CC + tid]; vs2[tid] = pk2(v, v); }
    if (tid < CQ) { float v = g_Ksum[b*CQ + tid] + EPSV; kse2[tid] = pk2(v, v); }
    __syncthreads();

    int n0 = (blockIdx.x * 256 + tid) * 2;

    u64 q2[CQ];
#pragma unroll
    for (int m = 0; m < CQ; m++)
        q2[m] = *(const u64*)(g_Qn + (size_t)(b*CQ + m)*NN + n0);

    // tailor: sum over ALL 32 m
    u64 t0 = pk2((float)NN, (float)NN), t1 = 0ULL, t2 = 0ULL, t3 = 0ULL;
#pragma unroll
    for (int mh = 0; mh < 8; mh++) {
        ulonglong2 ke0 = ((const ulonglong2*)kse2)[2*mh];
        ulonglong2 ke1 = ((const ulonglong2*)kse2)[2*mh+1];
        t0 = fma2(q2[4*mh+0], ke0.x, t0);
        t1 = fma2(q2[4*mh+1], ke0.y, t1);
        t2 = fma2(q2[4*mh+2], ke1.x, t2);
        t3 = fma2(q2[4*mh+3], ke1.y, t3);
    }
    u64 tt = add2(add2(t0, t1), add2(t2, t3));
    float tl, th; upk2(tl, th, tt);
    float gm = __ldg(&gamma[0]);
    u64 scale2 = pk2(gm / tl, gm / th);

    float* op = out + (size_t)(b*CC)*NN + n0;
#pragma unroll 2
    for (int c = 0; c < CC; c++) {
        u64 a0 = vs2[c], a1 = 0ULL, a2 = 0ULL, a3 = 0ULL;
        const ulonglong2* row = (const ulonglong2*)(mat2 + c*34);
#pragma unroll
        for (int m4 = 0; m4 < 8; m4++) {
            ulonglong2 w0 = row[2*m4];
            ulonglong2 w1 = row[2*m4+1];
            a0 = fma2(w0.x, q2[4*m4],   a0);
            a1 = fma2(w0.y, q2[4*m4+1], a1);
            a2 = fma2(w1.x, q2[4*m4+2], a2);
            a3 = fma2(w1.y, q2[4*m4+3], a3);
        }
        u64 res = mul2(add2(add2(a0, a1), add2(a2, a3)), scale2);
        *(u64*)(op + (size_t)c*NN) = res;
    }
}

extern "C" void kernel_launch(void* const* d_in, const int* in_sizes, int n_in,
                              void* d_out, int out_size) {
    const float* x     = (const float*)d_in[0];
    const float* x1    = (const float*)d_in[1];
    const float* Wq    = (const float*)d_in[2];
    const float* bq    = (const float*)d_in[3];
    const float* Wk    = (const float*)d_in[4];
    const float* bk    = (const float*)d_in[5];
    const float* Wv    = (const float*)d_in[6];
    const float* bv    = (const float*)d_in[7];
    const float* gamma = (const float*)d_in[8];
    float* out = (float*)d_out;

    const int qk_smem  = CC*64*8 + 192*128*4 + 1024*4;   // 98304+98304+4096 = 200704 B
    const int fin_smem = (192*34 + 192 + 32) * 8;        // 54016 B
    cudaFuncSetAttribute(qk_kernel, cudaFuncAttributeMaxDynamicSharedMemorySize, qk_smem);
    cudaFuncSetAttribute(final_kernel, cudaFuncAttributeMaxDynamicSharedMemorySize, fin_smem);

    zero_kernel<<<96, 256>>>();
    qk_kernel<<<dim3(NN/128, BN), 256, qk_smem>>>(x1, Wq, bq, Wk, bk);
    m1_kernel<<<dim3(NN/512, BN), 192>>>(x);
    mat_kernel<<<dim3(BN, 16), 192>>>(Wv, bv);
    final_kernel<<<dim3(NN/512, BN), 256, fin_smem>>>(out, gamma);
}

// round 8
// speedup vs baseline: 1.5862x; 1.0487x over previous
#include <cuda_runtime.h>

#define BN 8
#define CC 192
#define CQ 32
#define NN 16384
#define EPSV 1e-6f

typedef unsigned long long u64;

__device__ __forceinline__ u64 pk2(float lo, float hi) {
    u64 r; asm("mov.b64 %0,{%1,%2};" : "=l"(r) : "f"(lo), "f"(hi)); return r;
}
__device__ __forceinline__ void upk2(float& lo, float& hi, u64 v) {
    asm("mov.b64 {%0,%1},%2;" : "=f"(lo), "=f"(hi) : "l"(v));
}
__device__ __forceinline__ u64 fma2(u64 a, u64 b, u64 c) {
    u64 d; asm("fma.rn.f32x2 %0,%1,%2,%3;" : "=l"(d) : "l"(a), "l"(b), "l"(c)); return d;
}
__device__ __forceinline__ u64 mul2(u64 a, u64 b) {
    u64 d; asm("mul.rn.f32x2 %0,%1,%2;" : "=l"(d) : "l"(a), "l"(b)); return d;
}
__device__ __forceinline__ u64 add2(u64 a, u64 b) {
    u64 d; asm("add.rn.f32x2 %0,%1,%2;" : "=l"(d) : "l"(a), "l"(b)); return d;
}

// Scratch (device globals: no allocation allowed)
__device__ float g_Qn[BN*CQ*NN];
__device__ float g_Kn[BN*CQ*NN];
__device__ float g_Ksum[BN*CQ];
__device__ float g_xsum[BN*CC];
__device__ float g_M1[BN*CQ*CC];
__device__ float g_mat[BN*CQ*CC];
__device__ float g_vsum[BN*CC];

__global__ void zero_kernel() {
    int i = blockIdx.x * blockDim.x + threadIdx.x;
    int stride = gridDim.x * blockDim.x;
    for (int j = i; j < BN*CQ; j += stride) g_Ksum[j] = 0.f;
    for (int j = i; j < BN*CC; j += stride) { g_xsum[j] = 0.f; g_vsum[j] = 0.f; }
    for (int j = i; j < BN*CQ*CC; j += stride) { g_M1[j] = 0.f; g_mat[j] = 0.f; }
}

// ---------------------------------------------------------------------------
// Q/K projection + L2 norm, packed f32x2 over n. PERSISTENT TILES:
// grid (16, 8); each CTA owns 8 consecutive 128-n tiles; weights staged once.
// Block 256, thread tile 8m x 4n. tid = qk*128 + mg*32 + nt.
// smem: wqT/wkT [c][36] f32 (48KB) + xs[192][128] (96KB) + psum (4KB) = 148KB.
// ---------------------------------------------------------------------------
__global__ void __launch_bounds__(256, 1) qk_kernel(
    const float* __restrict__ x1,
    const float* __restrict__ Wq, const float* __restrict__ bq,
    const float* __restrict__ Wk, const float* __restrict__ bk)
{
    extern __shared__ float sm[];
    float* wqT  = sm;                 // 192*36
    float* wkT  = wqT + 192*36;       // 192*36
    float* xs   = wkT + 192*36;       // 192*128
    float* psum = xs + 192*128;       // 1024

    int tid = threadIdx.x;
    int b   = blockIdx.y;

    // stage transposed weights once per CTA
    for (int i = tid; i < CQ*CC; i += 256) {
        int m = i / CC, c = i % CC;
        wqT[c*36 + m] = Wq[i];
        wkT[c*36 + m] = Wk[i];
    }

    int qk = tid >> 7;
    int r  = tid & 127;
    int mg = r >> 5;
    int nt = r & 31;
    int n0 = nt * 4;

    const float* wT   = qk ? wkT : wqT;
    const float* bias = qk ? bk : bq;
    float b8[8];
#pragma unroll
    for (int mi = 0; mi < 8; mi++) b8[mi] = __ldg(&bias[mg*8 + mi]);

    for (int t = 0; t < 8; t++) {
        int nb = (blockIdx.x * 8 + t) * 128;

        // stage x1 tile [c][n]
        __syncthreads();   // previous tile's psum reads / xs reads complete
        for (int i = tid; i < 192*32; i += 256) {
            int c = i >> 5, jj = i & 31;
            *(float4*)(xs + c*128 + 4*jj) =
                *(const float4*)(x1 + (size_t)(b*CC + c)*NN + nb + 4*jj);
        }
        __syncthreads();

        u64 acc[16];   // [mi][pr]: pr0=(n0,n1), pr1=(n2,n3)
#pragma unroll
        for (int mi = 0; mi < 8; mi++) {
            u64 b2 = pk2(b8[mi], b8[mi]);
            acc[mi*2] = b2; acc[mi*2+1] = b2;
        }

#pragma unroll 2
        for (int c = 0; c < CC; c++) {
            ulonglong2 xv = *(const ulonglong2*)(xs + c*128 + n0);
            const float4* wr = (const float4*)(wT + c*36 + mg*8);
            float4 w0 = wr[0];
            float4 w1 = wr[1];
            u64 d0 = pk2(w0.x, w0.x), d1 = pk2(w0.y, w0.y);
            u64 d2 = pk2(w0.z, w0.z), d3 = pk2(w0.w, w0.w);
            u64 d4 = pk2(w1.x, w1.x), d5 = pk2(w1.y, w1.y);
            u64 d6 = pk2(w1.z, w1.z), d7 = pk2(w1.w, w1.w);
            acc[0]  = fma2(d0, xv.x, acc[0]);  acc[1]  = fma2(d0, xv.y, acc[1]);
            acc[2]  = fma2(d1, xv.x, acc[2]);  acc[3]  = fma2(d1, xv.y, acc[3]);
            acc[4]  = fma2(d2, xv.x, acc[4]);  acc[5]  = fma2(d2, xv.y, acc[5]);
            acc[6]  = fma2(d3, xv.x, acc[6]);  acc[7]  = fma2(d3, xv.y, acc[7]);
            acc[8]  = fma2(d4, xv.x, acc[8]);  acc[9]  = fma2(d4, xv.y, acc[9]);
            acc[10] = fma2(d5, xv.x, acc[10]); acc[11] = fma2(d5, xv.y, acc[11]);
            acc[12] = fma2(d6, xv.x, acc[12]); acc[13] = fma2(d6, xv.y, acc[13]);
            acc[14] = fma2(d7, xv.x, acc[14]); acc[15] = fma2(d7, xv.y, acc[15]);
        }

        // partial sum of squares per n (this thread's 8 m's)
        float s0 = 0.f, s1 = 0.f, s2 = 0.f, s3 = 0.f;
#pragma unroll
        for (int mi = 0; mi < 8; mi++) {
            float l0, h0, l1, h1;
            upk2(l0, h0, acc[mi*2]);
            upk2(l1, h1, acc[mi*2+1]);
            s0 += l0*l0; s1 += h0*h0; s2 += l1*l1; s3 += h1*h1;
        }
        psum[tid*4+0] = s0; psum[tid*4+1] = s1;
        psum[tid*4+2] = s2; psum[tid*4+3] = s3;
        __syncthreads();

        float t0 = 0.f, t1 = 0.f, t2 = 0.f, t3 = 0.f;
#pragma unroll
        for (int g = 0; g < 4; g++) {
            int p = (qk*128 + g*32 + nt)*4;
            t0 += psum[p]; t1 += psum[p+1]; t2 += psum[p+2]; t3 += psum[p+3];
        }
        u64 inv01 = pk2(rsqrtf(t0), rsqrtf(t1));
        u64 inv23 = pk2(rsqrtf(t2), rsqrtf(t3));

        if (qk == 0) {
#pragma unroll
            for (int mi = 0; mi < 8; mi++) {
                ulonglong2 st;
                st.x = mul2(acc[mi*2],   inv01);
                st.y = mul2(acc[mi*2+1], inv23);
                *(ulonglong2*)(g_Qn + (size_t)(b*CQ + mg*8 + mi)*NN + nb + n0) = st;
            }
        } else {
#pragma unroll
            for (int mi = 0; mi < 8; mi++) {
                ulonglong2 st;
                st.x = mul2(acc[mi*2],   inv01);
                st.y = mul2(acc[mi*2+1], inv23);
                *(ulonglong2*)(g_Kn + (size_t)(b*CQ + mg*8 + mi)*NN + nb + n0) = st;
                float l0, h0, l1, h1;
                upk2(l0, h0, st.x); upk2(l1, h1, st.y);
                float kv = (l0 + h0) + (l1 + h1);
#pragma unroll
                for (int o = 16; o; o >>= 1) kv += __shfl_xor_sync(0xffffffffu, kv, o);
                if (nt == 0) atomicAdd(&g_Ksum[b*CQ + mg*8 + mi], kv);
            }
        }
    }
}

// ---------------------------------------------------------------------------
// M1[b,m,p] = sum_n Kn[b,m,n]*x[b,p,n]; xsum[b,p] = sum_n x[b,p,n]
// Block 192: tid = jh*96 + mh*48 + pq. Thread tile: 16 m x 4 p, packed over p.
// (R3 version — single buffer, occupancy provides overlap.)
// ---------------------------------------------------------------------------
__global__ void __launch_bounds__(192, 2) m1_kernel(const float* __restrict__ x)
{
    __shared__ float xs[32*196];      // [j][p], pad 196
    __shared__ u64 kst2[32*34];       // [j][m] duplicated {k,k}, pad 34

    int tid = threadIdx.x;
    int b = blockIdx.y;
    int nbase = blockIdx.x * 512;

    int jh = tid / 96;
    int rr = tid % 96;
    int mh = rr / 48;
    int pq = rr % 48;

    u64 a[32];
#pragma unroll
    for (int k = 0; k < 32; k++) a[k] = 0ULL;
    u64 xsA = 0ULL, xsB = 0ULL;

    for (int s = 0; s < 16; s++) {
        int n0 = nbase + s*32;
        __syncthreads();
        for (int i = tid; i < CC*32; i += 192) {
            int p = i >> 5, j = i & 31;
            xs[j*196 + p] = x[(size_t)(b*CC + p)*NN + n0 + j];
        }
        for (int i = tid; i < CQ*32; i += 192) {
            int m = i >> 5, j = i & 31;
            float v = g_Kn[(size_t)(b*CQ + m)*NN + n0 + j];
            kst2[j*34 + m] = pk2(v, v);
        }
        __syncthreads();

        int jbeg = jh * 16;
#pragma unroll 2
        for (int jj = 0; jj < 16; jj++) {
            int j = jbeg + jj;
            ulonglong2 xv = *(const ulonglong2*)(xs + j*196 + 4*pq);
            xsA = add2(xsA, xv.x);
            xsB = add2(xsB, xv.y);
            const ulonglong2* kr = (const ulonglong2*)(kst2 + j*34 + mh*16);
#pragma unroll
            for (int mm = 0; mm < 8; mm++) {
                ulonglong2 kk = kr[mm];
                a[mm*4+0] = fma2(kk.x, xv.x, a[mm*4+0]);
                a[mm*4+1] = fma2(kk.x, xv.y, a[mm*4+1]);
                a[mm*4+2] = fma2(kk.y, xv.x, a[mm*4+2]);
                a[mm*4+3] = fma2(kk.y, xv.y, a[mm*4+3]);
            }
        }
    }

    // combine jh halves via smem, then atomics from jh==0
    __syncthreads();
    u64* comb = (u64*)xs;   // 96*32 u64 = 24576 B <= xs size
    int slot = mh*48 + pq;
    if (jh == 1) {
#pragma unroll
        for (int k = 0; k < 32; k++) comb[slot*32 + k] = a[k];
    }
    __syncthreads();
    if (jh == 0) {
#pragma unroll
        for (int k = 0; k < 32; k++) {
            u64 t = add2(a[k], comb[slot*32 + k]);
            float lo, hi; upk2(lo, hi, t);
            int m = mh*16 + ((k >> 2) << 1) + ((k >> 1) & 1);
            int p = 4*pq + ((k & 1) << 1);
            atomicAdd(&g_M1[(b*CQ + m)*CC + p],     lo);
            atomicAdd(&g_M1[(b*CQ + m)*CC + p + 1], hi);
        }
    }
    if (mh == 0) {
        float l0, h0, l1, h1;
        upk2(l0, h0, xsA); upk2(l1, h1, xsB);
        atomicAdd(&g_xsum[b*CC + 4*pq + 0], l0);
        atomicAdd(&g_xsum[b*CC + 4*pq + 1], h0);
        atomicAdd(&g_xsum[b*CC + 4*pq + 2], l1);
        atomicAdd(&g_xsum[b*CC + 4*pq + 3], h1);
    }
}

// ---------------------------------------------------------------------------
// matrix[b,m,c] = sum_p Wv[c,p]*M1[b,m,p] + bv[c]*Ksum[b,m]
// vsum[b,c]    = sum_p Wv[c,p]*xsum[b,p] + N*bv[c]
// grid (BN, 16), block 192 (one thread per c), 12 p per block.
// ---------------------------------------------------------------------------
__global__ void __launch_bounds__(192) mat_kernel(
    const float* __restrict__ Wv, const float* __restrict__ bv)
{
    __shared__ float m1t[CC][36];   // [p][m]
    __shared__ float xs_s[CC];
    int tid = threadIdx.x;
    int b  = blockIdx.x;
    int pg = blockIdx.y;  // 0..15, 12 p's each

    for (int i = tid; i < CQ*CC; i += 192) {
        int m = i / CC, p = i % CC;
        m1t[p][m] = g_M1[b*CQ*CC + i];
    }
    xs_s[tid] = g_xsum[b*CC + tid];
    __syncthreads();

    int c = tid;
    float accm[CQ];
#pragma unroll
    for (int m = 0; m < CQ; m++) accm[m] = 0.f;
    float vs = 0.f;

    for (int p = pg*12; p < (pg+1)*12; p++) {
        float wv = __ldg(&Wv[c*CC + p]);
        vs += wv * xs_s[p];
        const float4* row = (const float4*)&m1t[p][0];
#pragma unroll
        for (int m4 = 0; m4 < 8; m4++) {
            float4 mv = row[m4];
            accm[m4*4+0] += wv*mv.x;
            accm[m4*4+1] += wv*mv.y;
            accm[m4*4+2] += wv*mv.z;
            accm[m4*4+3] += wv*mv.w;
        }
    }
    if (pg == 0) {
        float bvc = __ldg(&bv[c]);
        vs += (float)NN * bvc;
#pragma unroll
        for (int m = 0; m < CQ; m++) accm[m] += bvc * g_Ksum[b*CQ + m];
    }
    atomicAdd(&g_vsum[b*CC + c], vs);
#pragma unroll
    for (int m = 0; m < CQ; m++) atomicAdd(&g_mat[(b*CQ + m)*CC + c], accm[m]);
}

// ---------------------------------------------------------------------------
// out[b,c,n] = gamma*tailor[b,n]*(vsum[b,c] + sum_m Qn[b,m,n]*matrix[b,m,c])
// 4 n per thread (two f32x2 lanes). Block 128, grid (NN/512, BN).
// Per c: 16 broadcast LDS.128 against 64 FFMA2 -> FMA-bound.
// ---------------------------------------------------------------------------
__global__ void __launch_bounds__(128, 2) final_kernel(
    float* __restrict__ out, const float* __restrict__ gamma)
{
    extern __shared__ u64 smf[];
    u64* mat2 = smf;                 // 192*34
    u64* vs2  = mat2 + 192*34;       // 192
    u64* kse2 = vs2 + 192;           // 32

    int tid = threadIdx.x;
    int b = blockIdx.y;

    for (int i = tid; i < CQ*CC; i += 128) {
        int m = i / CC, c = i % CC;
        float v = g_mat[b*CQ*CC + i];
        mat2[c*34 + m] = pk2(v, v);
    }
    for (int i = tid; i < CC; i += 128) { float v = g_vsum[b*CC + i]; vs2[i] = pk2(v, v); }
    if (tid < CQ) { float v = g_Ksum[b*CQ + tid] + EPSV; kse2[tid] = pk2(v, v); }
    __syncthreads();

    int n0 = (blockIdx.x * 128 + tid) * 4;

    u64 qA[CQ], qB[CQ];   // qA = (n0,n1), qB = (n2,n3)
#pragma unroll
    for (int m = 0; m < CQ; m++) {
        ulonglong2 qq = *(const ulonglong2*)(g_Qn + (size_t)(b*CQ + m)*NN + n0);
        qA[m] = qq.x; qB[m] = qq.y;
    }

    // tailor over all 32 m, 4 chains
    u64 nn2 = pk2((float)NN, (float)NN);
    u64 ta0 = nn2, ta1 = 0ULL, tb0 = nn2, tb1 = 0ULL;
#pragma unroll
    for (int mh = 0; mh < 16; mh++) {
        ulonglong2 ke = ((const ulonglong2*)kse2)[mh];
        ta0 = fma2(qA[2*mh+0], ke.x, ta0);
        ta1 = fma2(qA[2*mh+1], ke.y, ta1);
        tb0 = fma2(qB[2*mh+0], ke.x, tb0);
        tb1 = fma2(qB[2*mh+1], ke.y, tb1);
    }
    u64 tta = add2(ta0, ta1), ttb = add2(tb0, tb1);
    float tl0, th0, tl1, th1;
    upk2(tl0, th0, tta); upk2(tl1, th1, ttb);
    float gm = __ldg(&gamma[0]);
    u64 sA = pk2(gm / tl0, gm / th0);
    u64 sB = pk2(gm / tl1, gm / th1);

    float* op = out + (size_t)(b*CC)*NN + n0;
#pragma unroll 2
    for (int c = 0; c < CC; c++) {
        u64 a0 = vs2[c], a1 = 0ULL, a2 = 0ULL, a3 = 0ULL;
        u64 b0 = vs2[c], b1 = 0ULL, b2 = 0ULL, b3 = 0ULL;
        const ulonglong2* row = (const ulonglong2*)(mat2 + c*34);
#pragma unroll
        for (int m4 = 0; m4 < 8; m4++) {
            ulonglong2 w0 = row[2*m4];
            ulonglong2 w1 = row[2*m4+1];
            a0 = fma2(w0.x, qA[4*m4+0], a0);
            a1 = fma2(w0.y, qA[4*m4+1], a1);
            a2 = fma2(w1.x, qA[4*m4+2], a2);
            a3 = fma2(w1.y, qA[4*m4+3], a3);
            b0 = fma2(w0.x, qB[4*m4+0], b0);
            b1 = fma2(w0.y, qB[4*m4+1], b1);
            b2 = fma2(w1.x, qB[4*m4+2], b2);
            b3 = fma2(w1.y, qB[4*m4+3], b3);
        }
        ulonglong2 res;
        res.x = mul2(add2(add2(a0, a1), add2(a2, a3)), sA);
        res.y = mul2(add2(add2(b0, b1), add2(b2, b3)), sB);
        *(ulonglong2*)(op + (size_t)c*NN) = res;
    }
}

extern "C" void kernel_launch(void* const* d_in, const int* in_sizes, int n_in,
                              void* d_out, int out_size) {
    const float* x     = (const float*)d_in[0];
    const float* x1    = (const float*)d_in[1];
    const float* Wq    = (const float*)d_in[2];
    const float* bq    = (const float*)d_in[3];
    const float* Wk    = (const float*)d_in[4];
    const float* bk    = (const float*)d_in[5];
    const float* Wv    = (const float*)d_in[6];
    const float* bv    = (const float*)d_in[7];
    const float* gamma = (const float*)d_in[8];
    float* out = (float*)d_out;

    const int qk_smem  = (2*192*36 + 192*128 + 1024) * 4;   // 151552 B
    const int fin_smem = (192*34 + 192 + 32) * 8;           // 54016 B
    cudaFuncSetAttribute(qk_kernel, cudaFuncAttributeMaxDynamicSharedMemorySize, qk_smem);
    cudaFuncSetAttribute(final_kernel, cudaFuncAttributeMaxDynamicSharedMemorySize, fin_smem);

    zero_kernel<<<96, 256>>>();
    qk_kernel<<<dim3(16, BN), 256, qk_smem>>>(x1, Wq, bq, Wk, bk);
    m1_kernel<<<dim3(NN/512, BN), 192>>>(x);
    mat_kernel<<<dim3(BN, 16), 192>>>(Wv, bv);
    final_kernel<<<dim3(NN/512, BN), 128, fin_smem>>>(out, gamma);
}